// round 14
// baseline (speedup 1.0000x reference)
#include <cuda_runtime.h>
#include <cuda_bf16.h>
#include <cstdint>
#include <math.h>

#define BB  4
#define LL  2048
#define DD  1024
#define HH  16
#define DHH 64
#define MTOT   (BB*LL)            // 8192
#define NPLANE (BB*HH*LL*DHH)     // 8388608
// Q premul: attention scale folded with log2(e) -> softmax in exp2 domain
#define QPRE (0.125f * 1.4426950408889634f)

// ---------------- scratch (__device__ globals are the sanctioned mechanism) --
static __device__ __nv_bfloat16 g_Qh[NPLANE], g_Ql[NPLANE];
static __device__ __nv_bfloat16 g_Kh[NPLANE], g_Kl[NPLANE];
static __device__ __nv_bfloat16 g_Vh[NPLANE], g_Vl[NPLANE];
static __device__ __nv_bfloat16 g_ah[MTOT*DD];   // activation hi plane
static __device__ __nv_bfloat16 g_al[MTOT*DD];   // activation lo plane
static __device__ __nv_bfloat16 g_wh[DD*DD];     // weight hi plane
static __device__ __nv_bfloat16 g_wl[DD*DD];     // weight lo plane
static __device__ int g_idx[BB*LL];              // unmasked key indices (compacted)
static __device__ int g_cnt[BB];                 // unmasked key count per batch

// ---------------- helpers (sm_80-era PTX, valid at .target sm_103) ----------
__device__ __forceinline__ uint32_t smem_u32(const void* p) {
    uint32_t a;
    asm("{ .reg .u64 t; cvta.to.shared.u64 t, %1; cvt.u32.u64 %0, t; }" : "=r"(a) : "l"(p));
    return a;
}
__device__ __forceinline__ void ldsm_x4(uint32_t* r, uint32_t addr) {
    asm volatile("ldmatrix.sync.aligned.m8n8.x4.shared.b16 {%0,%1,%2,%3}, [%4];"
        : "=r"(r[0]), "=r"(r[1]), "=r"(r[2]), "=r"(r[3]) : "r"(addr));
}
__device__ __forceinline__ void ldsm_x4_t(uint32_t* r, uint32_t addr) {
    asm volatile("ldmatrix.sync.aligned.m8n8.x4.trans.shared.b16 {%0,%1,%2,%3}, [%4];"
        : "=r"(r[0]), "=r"(r[1]), "=r"(r[2]), "=r"(r[3]) : "r"(addr));
}
__device__ __forceinline__ void mma16816(float* d, const uint32_t* a, const uint32_t* b) {
    asm volatile("mma.sync.aligned.m16n8k16.row.col.f32.bf16.bf16.f32 "
        "{%0,%1,%2,%3}, {%4,%5,%6,%7}, {%8,%9}, {%0,%1,%2,%3};"
        : "+f"(d[0]), "+f"(d[1]), "+f"(d[2]), "+f"(d[3])
        : "r"(a[0]), "r"(a[1]), "r"(a[2]), "r"(a[3]), "r"(b[0]), "r"(b[1]));
}
__device__ __forceinline__ float ex2f(float x) {
    float y; asm("ex2.approx.ftz.f32 %0, %1;" : "=f"(y) : "f"(x)); return y;
}
__device__ __forceinline__ void split_pair(float a0, float a1, uint32_t& hi, uint32_t& lo) {
    __nv_bfloat162 H = __floats2bfloat162_rn(a0, a1);
    __nv_bfloat162 L = __floats2bfloat162_rn(a0 - __bfloat162float(H.x),
                                             a1 - __bfloat162float(H.y));
    hi = *reinterpret_cast<uint32_t*>(&H);
    lo = *reinterpret_cast<uint32_t*>(&L);
}
__device__ __forceinline__ void cp_async16(uint32_t smem_addr, const void* gptr) {
    asm volatile("cp.async.cg.shared.global [%0], [%1], 16;"
        :: "r"(smem_addr), "l"(gptr) : "memory");
}
#define CP_COMMIT() asm volatile("cp.async.commit_group;" ::: "memory")

// ---------------------------------------------------------------------------
// Per-batch compaction of unmasked key indices (prefix scan over 2048 ints).
// ---------------------------------------------------------------------------
__global__ __launch_bounds__(256)
void build_idx(const int* __restrict__ mask)
{
    __shared__ int ps[256];
    const int b = blockIdx.x, t = threadIdx.x;
    const int* m = mask + b * LL;
    int loc[8], c = 0;
#pragma unroll
    for (int i = 0; i < 8; i++) { loc[i] = m[t * 8 + i]; c += (loc[i] == 1); }
    ps[t] = c;
    __syncthreads();
    for (int off = 1; off < 256; off <<= 1) {
        int u = (t >= off) ? ps[t - off] : 0;
        __syncthreads();
        ps[t] += u;
        __syncthreads();
    }
    int pos = ps[t] - c;        // exclusive prefix
    const int total = ps[255];
#pragma unroll
    for (int i = 0; i < 8; i++)
        if (loc[i] == 1) g_idx[b * LL + (pos++)] = t * 8 + i;
    if (t == 0) {
        g_cnt[b] = total;
        int pad = (total + 63) & ~63;
        for (int i = total; i < pad; i++) g_idx[b * LL + i] = 0;
    }
}

// ---------------------------------------------------------------------------
// fp32 -> (hi, lo) bf16 split conversion
// ---------------------------------------------------------------------------
__global__ __launch_bounds__(256)
void conv_split(const float* __restrict__ in,
                __nv_bfloat16* __restrict__ hi,
                __nv_bfloat16* __restrict__ lo, int n4)
{
    int i = blockIdx.x * blockDim.x + threadIdx.x;
    if (i >= n4) return;
    float4 v = ((const float4*)in)[i];
    uint32_t h01, l01, h23, l23;
    split_pair(v.x, v.y, h01, l01);
    split_pair(v.z, v.w, h23, l23);
    uint32_t* H = (uint32_t*)(hi + 4 * (size_t)i);
    uint32_t* L = (uint32_t*)(lo + 4 * (size_t)i);
    H[0] = h01; H[1] = h23;
    L[0] = l01; L[1] = l23;
}

// ---------------------------------------------------------------------------
// HMMA bf16-split GEMM: C[m,n] = sum_k A[m,k]*W[n,k]
// cp.async 2-stage pipeline; term-major MMA issue (16 indep accs per term).
// MODE 0: fp32 C row-major. MODE 1: (hi,lo) bf16 planes, head-split, *premul.
// ---------------------------------------------------------------------------
#define ROWB      80
#define PLANE_B   (128*ROWB)
#define STAGE_B   (4*PLANE_B)
#define GSM_TOTAL (2*STAGE_B)

template<int MODE>
__global__ __launch_bounds__(256)
void gemm_mma(const __nv_bfloat16* __restrict__ Ahp, const __nv_bfloat16* __restrict__ Alp,
              const __nv_bfloat16* __restrict__ Whp, const __nv_bfloat16* __restrict__ Wlp,
              float* __restrict__ Cf,
              __nv_bfloat16* __restrict__ Ch, __nv_bfloat16* __restrict__ Cl,
              float premul)
{
    extern __shared__ char smem[];
    const uint32_t sb = smem_u32(smem);
    const int t    = threadIdx.x;
    const int lane = t & 31;
    const int wid  = t >> 5;
    const int wm   = (wid & 3) * 32;
    const int wn   = (wid >> 2) * 64;
    const int bm   = blockIdx.y * 128;
    const int bn   = blockIdx.x * 128;

    const int r0 = t >> 2,         c80 = (t & 3) * 8;
    const int r1 = (t + 256) >> 2, c81 = ((t + 256) & 3) * 8;

    const __nv_bfloat16* src4[4] = { Ahp + (size_t)bm * 1024, Alp + (size_t)bm * 1024,
                                     Whp + (size_t)bn * 1024, Wlp + (size_t)bn * 1024 };

    float acc[2][8][4];
#pragma unroll
    for (int i = 0; i < 2; i++)
#pragma unroll
        for (int j = 0; j < 8; j++)
#pragma unroll
            for (int c = 0; c < 4; c++) acc[i][j][c] = 0.f;

    const uint32_t a_row = lane & 15, a_half = (lane >> 4) * 8;
    const uint32_t w_mat = lane >> 3, w_j = lane & 7;
    const uint32_t w_rowoff = (w_mat >> 1) * 8 + w_j;
    const uint32_t w_koff   = (w_mat & 1) * 8;

    auto cp_load = [&](int st, int chunk) {
        const int k0 = chunk * 32;
        const uint32_t base = sb + st * STAGE_B;
#pragma unroll
        for (int p = 0; p < 4; p++) {
            cp_async16(base + p * PLANE_B + r0 * ROWB + c80 * 2,
                       src4[p] + (size_t)r0 * 1024 + k0 + c80);
            cp_async16(base + p * PLANE_B + r1 * ROWB + c81 * 2,
                       src4[p] + (size_t)r1 * 1024 + k0 + c81);
        }
    };

    cp_load(0, 0);
    CP_COMMIT();

    for (int it = 0; it < 32; it++) {
        const int st = it & 1;
        __syncthreads();                 // all warps done reading stage st (it-2)
        if (it + 1 < 32) {
            cp_load(st ^ 1, it + 1);
            CP_COMMIT();
            asm volatile("cp.async.wait_group 1;" ::: "memory");
        } else {
            asm volatile("cp.async.wait_group 0;" ::: "memory");
        }
        __syncthreads();                 // stage st data visible

        const uint32_t stage = sb + st * STAGE_B;
        const uint32_t ah_b = stage + 0 * PLANE_B;
        const uint32_t al_b = stage + 1 * PLANE_B;
        const uint32_t wh_b = stage + 2 * PLANE_B;
        const uint32_t wl_b = stage + 3 * PLANE_B;

#pragma unroll
        for (int ks = 0; ks < 32; ks += 16) {
            uint32_t ah[2][4], al[2][4], wh[4][4], wl[4][4];
#pragma unroll
            for (int mt = 0; mt < 2; mt++) {
                uint32_t ra = (wm + mt * 16 + a_row) * ROWB + (ks + a_half) * 2;
                ldsm_x4(ah[mt], ah_b + ra);
                ldsm_x4(al[mt], al_b + ra);
            }
#pragma unroll
            for (int np = 0; np < 4; np++) {
                uint32_t rw = (wn + np * 16 + w_rowoff) * ROWB + (ks + w_koff) * 2;
                ldsm_x4(wh[np], wh_b + rw);
                ldsm_x4(wl[np], wl_b + rw);
            }
            // term-major issue: 16 independent accumulators between reuse
#pragma unroll
            for (int mt = 0; mt < 2; mt++)
#pragma unroll
                for (int nt = 0; nt < 8; nt++)
                    mma16816(acc[mt][nt], ah[mt], &wh[nt >> 1][(nt & 1) * 2]);
#pragma unroll
            for (int mt = 0; mt < 2; mt++)
#pragma unroll
                for (int nt = 0; nt < 8; nt++)
                    mma16816(acc[mt][nt], ah[mt], &wl[nt >> 1][(nt & 1) * 2]);
#pragma unroll
            for (int mt = 0; mt < 2; mt++)
#pragma unroll
                for (int nt = 0; nt < 8; nt++)
                    mma16816(acc[mt][nt], al[mt], &wh[nt >> 1][(nt & 1) * 2]);
        }
    }

    const int erow = lane >> 2;
    const int ecol = (lane & 3) * 2;
#pragma unroll
    for (int mt = 0; mt < 2; mt++)
#pragma unroll
        for (int nt = 0; nt < 8; nt++)
#pragma unroll
            for (int half = 0; half < 2; half++) {
                int m = bm + wm + mt * 16 + erow + half * 8;
                int n = bn + wn + nt * 8 + ecol;
                float a0 = acc[mt][nt][half * 2 + 0];
                float a1 = acc[mt][nt][half * 2 + 1];
                if (MODE == 1) {
                    a0 *= premul; a1 *= premul;
                    uint32_t hi, lo;
                    split_pair(a0, a1, hi, lo);
                    int bidx = m >> 11, l = m & 2047;
                    int h = n >> 6, dh = n & 63;
                    size_t idx = (((size_t)(bidx * HH + h) * LL + l) << 6) + dh;
                    *(uint32_t*)(Ch + idx) = hi;
                    *(uint32_t*)(Cl + idx) = lo;
                } else {
                    *(float2*)(Cf + (size_t)m * 1024 + n) = make_float2(a0, a1);
                }
            }
}

// ---------------------------------------------------------------------------
// HMMA flash attention over COMPACTED (unmasked) keys, cp.async double-buffer.
// Term-major MMA issue in QK^T and PV. CTA = 128 q rows of one (b,h).
// ---------------------------------------------------------------------------
#define AT_RS    144                  // smem row stride bytes (72 bf16)
#define AT_QH    0
#define AT_QL    18432
#define AT_KVB   36864                // KV stage base
#define KV_STAGE 36864
#define KV_KH    0
#define KV_KL    9216
#define KV_VH    18432
#define KV_VL    27648
#define AT_BIAS  (AT_KVB + 2*KV_STAGE)   // 110592; bias[2][64] floats
#define AT_SMEM  (AT_BIAS + 512)

__global__ __launch_bounds__(256)
void attn_mma(__nv_bfloat16* __restrict__ Oh, __nv_bfloat16* __restrict__ Ol)
{
    extern __shared__ char smc[];
    const uint32_t sb = smem_u32(smc);
    const int t = threadIdx.x, lane = t & 31, wid = t >> 5;
    const int wm = wid * 16;
    const int bh = blockIdx.y;
    const int b  = bh >> 4, h = bh & 15;
    const int r0 = blockIdx.x * 128;
    const size_t pbase = (size_t)bh * LL * DHH;

    const __nv_bfloat16* KH = g_Kh + pbase;
    const __nv_bfloat16* KL = g_Kl + pbase;
    const __nv_bfloat16* VH = g_Vh + pbase;
    const __nv_bfloat16* VL = g_Vl + pbase;

    const int nk     = g_cnt[b];
    const int ntiles = (nk + 63) >> 6;
    const int* idxp  = g_idx + b * LL;

    auto kv_load = [&](int stage, int tile) {
        const uint32_t kvb = sb + AT_KVB + stage * KV_STAGE;
#pragma unroll
        for (int i = 0; i < 2; i++) {
            int slot = i * 256 + t;
            int row = slot >> 3, c8 = (slot & 7) * 8;
            int src = idxp[tile * 64 + row];          // compacted key index
            size_t g = (size_t)src * 64 + c8;
            uint32_t d = kvb + row * AT_RS + c8 * 2;
            cp_async16(d + KV_KH, KH + g);
            cp_async16(d + KV_KL, KL + g);
            cp_async16(d + KV_VH, VH + g);
            cp_async16(d + KV_VL, VL + g);
        }
    };

    // ---- async Q prologue ----
    {
        const __nv_bfloat16* qh = g_Qh + pbase + (size_t)r0 * 64;
        const __nv_bfloat16* ql = g_Ql + pbase + (size_t)r0 * 64;
#pragma unroll
        for (int i = 0; i < 4; i++) {
            int slot = i * 256 + t;
            int row = slot >> 3, c8 = (slot & 7) * 8;
            cp_async16(sb + AT_QH + row * AT_RS + c8 * 2, qh + (size_t)row * 64 + c8);
            cp_async16(sb + AT_QL + row * AT_RS + c8 * 2, ql + (size_t)row * 64 + c8);
        }
        CP_COMMIT();
    }
    kv_load(0, 0);
    CP_COMMIT();
    asm volatile("cp.async.wait_group 1;" ::: "memory");   // Q resident
    __syncthreads();

    // ---- persistent Q fragments ----
    uint32_t qfh[4][4], qfl[4][4];
    {
        uint32_t qa = sb + (wm + (lane & 15)) * AT_RS + (lane >> 4) * 16;
#pragma unroll
        for (int ks = 0; ks < 4; ks++) {
            ldsm_x4(qfh[ks], qa + AT_QH + ks * 32);
            ldsm_x4(qfl[ks], qa + AT_QL + ks * 32);
        }
    }

    const int qr = lane >> 2;
    const int qc = (lane & 3) * 2;
    const int w_mat = lane >> 3;
    const uint32_t kfo = ((w_mat >> 1) * 8 + (lane & 7)) * AT_RS + (w_mat & 1) * 16;
    const uint32_t vfo = ((w_mat & 1) * 8 + (lane & 7)) * AT_RS + (w_mat >> 1) * 16;

    float o[8][4];
#pragma unroll
    for (int i = 0; i < 8; i++)
#pragma unroll
        for (int c = 0; c < 4; c++) o[i][c] = 0.f;
    float mr0 = -1e30f, mr1 = -1e30f, lr0 = 0.f, lr1 = 0.f;

    float* biasp = (float*)(smc + AT_BIAS);

    for (int j = 0; j < ntiles; j++) {
        const int s = j & 1;
        __syncthreads();
        if (j + 1 < ntiles) {
            kv_load(s ^ 1, j + 1);
            CP_COMMIT();
        }
        if (t < 64) biasp[s * 64 + t] = (j * 64 + t < nk) ? 0.f : -1e9f;
        if (j + 1 < ntiles) asm volatile("cp.async.wait_group 1;" ::: "memory");
        else                asm volatile("cp.async.wait_group 0;" ::: "memory");
        __syncthreads();

        const uint32_t kvb = sb + AT_KVB + s * KV_STAGE;

        // ---- S = Q K^T (term-major: 8 indep accs per term) ----
        float sc[8][4];
#pragma unroll
        for (int i = 0; i < 8; i++)
#pragma unroll
            for (int c = 0; c < 4; c++) sc[i][c] = 0.f;

#pragma unroll
        for (int ks = 0; ks < 4; ks++) {
            uint32_t kh4[4][4], kl4[4][4];
#pragma unroll
            for (int g = 0; g < 4; g++) {
                uint32_t a = kvb + kfo + g * (16 * AT_RS) + ks * 32;
                ldsm_x4(kh4[g], a + KV_KH);
                ldsm_x4(kl4[g], a + KV_KL);
            }
#pragma unroll
            for (int nt = 0; nt < 8; nt++)
                mma16816(sc[nt], qfh[ks], &kh4[nt >> 1][(nt & 1) * 2]);
#pragma unroll
            for (int nt = 0; nt < 8; nt++)
                mma16816(sc[nt], qfh[ks], &kl4[nt >> 1][(nt & 1) * 2]);
#pragma unroll
            for (int nt = 0; nt < 8; nt++)
                mma16816(sc[nt], qfl[ks], &kh4[nt >> 1][(nt & 1) * 2]);
        }

        // ---- pad bias + online softmax (exp2 domain) ----
        float m0 = -1e30f, m1 = -1e30f;
#pragma unroll
        for (int nt = 0; nt < 8; nt++) {
            float b0 = biasp[s * 64 + nt * 8 + qc], b1 = biasp[s * 64 + nt * 8 + qc + 1];
            sc[nt][0] += b0; sc[nt][1] += b1; sc[nt][2] += b0; sc[nt][3] += b1;
            m0 = fmaxf(m0, fmaxf(sc[nt][0], sc[nt][1]));
            m1 = fmaxf(m1, fmaxf(sc[nt][2], sc[nt][3]));
        }
        m0 = fmaxf(m0, __shfl_xor_sync(0xffffffffu, m0, 1));
        m0 = fmaxf(m0, __shfl_xor_sync(0xffffffffu, m0, 2));
        m1 = fmaxf(m1, __shfl_xor_sync(0xffffffffu, m1, 1));
        m1 = fmaxf(m1, __shfl_xor_sync(0xffffffffu, m1, 2));

        float mn0 = fmaxf(mr0, m0), mn1 = fmaxf(mr1, m1);
        float al0 = ex2f(mr0 - mn0), al1 = ex2f(mr1 - mn1);
        mr0 = mn0; mr1 = mn1;
        lr0 *= al0; lr1 *= al1;
#pragma unroll
        for (int nt = 0; nt < 8; nt++) {
            sc[nt][0] = ex2f(sc[nt][0] - mn0);
            sc[nt][1] = ex2f(sc[nt][1] - mn0);
            sc[nt][2] = ex2f(sc[nt][2] - mn1);
            sc[nt][3] = ex2f(sc[nt][3] - mn1);
            lr0 += sc[nt][0] + sc[nt][1];
            lr1 += sc[nt][2] + sc[nt][3];
            o[nt][0] *= al0; o[nt][1] *= al0;
            o[nt][2] *= al1; o[nt][3] *= al1;
        }

        // ---- O += P V (hoisted V frags; term-major: 8 indep accs) ----
#pragma unroll
        for (int kk = 0; kk < 4; kk++) {
            const int j0 = kk * 2, j1 = kk * 2 + 1;
            uint32_t ph[4], pl[4];
            split_pair(sc[j0][0], sc[j0][1], ph[0], pl[0]);
            split_pair(sc[j0][2], sc[j0][3], ph[1], pl[1]);
            split_pair(sc[j1][0], sc[j1][1], ph[2], pl[2]);
            split_pair(sc[j1][2], sc[j1][3], ph[3], pl[3]);
            uint32_t vh4[4][4], vl4[4][4];
#pragma unroll
            for (int g = 0; g < 4; g++) {
                uint32_t a = kvb + vfo + kk * (16 * AT_RS) + g * 32;
                ldsm_x4_t(vh4[g], a + KV_VH);
                ldsm_x4_t(vl4[g], a + KV_VL);
            }
#pragma unroll
            for (int nt = 0; nt < 8; nt++)
                mma16816(o[nt], ph, &vh4[nt >> 1][(nt & 1) * 2]);
#pragma unroll
            for (int nt = 0; nt < 8; nt++)
                mma16816(o[nt], ph, &vl4[nt >> 1][(nt & 1) * 2]);
#pragma unroll
            for (int nt = 0; nt < 8; nt++)
                mma16816(o[nt], pl, &vh4[nt >> 1][(nt & 1) * 2]);
        }
    }

    // ---- finalize ----
    lr0 += __shfl_xor_sync(0xffffffffu, lr0, 1);
    lr0 += __shfl_xor_sync(0xffffffffu, lr0, 2);
    lr1 += __shfl_xor_sync(0xffffffffu, lr1, 1);
    lr1 += __shfl_xor_sync(0xffffffffu, lr1, 2);
    const float inv0 = 1.f / lr0, inv1 = 1.f / lr1;

    const size_t m0i = (size_t)b * LL + (r0 + wm + qr);
    const size_t m1i = m0i + 8;
#pragma unroll
    for (int nt = 0; nt < 8; nt++) {
        const int col = h * 64 + nt * 8 + qc;
        uint32_t hi, lo;
        split_pair(o[nt][0] * inv0, o[nt][1] * inv0, hi, lo);
        *(uint32_t*)(Oh + m0i * DD + col) = hi;
        *(uint32_t*)(Ol + m0i * DD + col) = lo;
        split_pair(o[nt][2] * inv1, o[nt][3] * inv1, hi, lo);
        *(uint32_t*)(Oh + m1i * DD + col) = hi;
        *(uint32_t*)(Ol + m1i * DD + col) = lo;
    }
}

// ---------------------------------------------------------------------------
// Launch: 0:q 1:k 2:v 3:mask 4:Wq 5:Wk 6:Wv 7:Wo ; out [B,L,D] fp32
// ---------------------------------------------------------------------------
extern "C" void kernel_launch(void* const* d_in, const int* in_sizes, int n_in,
                              void* d_out, int out_size)
{
    const float* q    = (const float*)d_in[0];
    const float* k    = (const float*)d_in[1];
    const float* v    = (const float*)d_in[2];
    const int*   mask = (const int*)  d_in[3];
    const float* Wq   = (const float*)d_in[4];
    const float* Wk   = (const float*)d_in[5];
    const float* Wv   = (const float*)d_in[6];
    const float* Wo   = (const float*)d_in[7];
    float* out = (float*)d_out;

    __nv_bfloat16 *ah, *al, *wh, *wl, *qh, *ql, *kh, *kl, *vh, *vl;
    cudaGetSymbolAddress((void**)&ah, g_ah);
    cudaGetSymbolAddress((void**)&al, g_al);
    cudaGetSymbolAddress((void**)&wh, g_wh);
    cudaGetSymbolAddress((void**)&wl, g_wl);
    cudaGetSymbolAddress((void**)&qh, g_Qh);
    cudaGetSymbolAddress((void**)&ql, g_Ql);
    cudaGetSymbolAddress((void**)&kh, g_Kh);
    cudaGetSymbolAddress((void**)&kl, g_Kl);
    cudaGetSymbolAddress((void**)&vh, g_Vh);
    cudaGetSymbolAddress((void**)&vl, g_Vl);

    cudaFuncSetAttribute(attn_mma, cudaFuncAttributeMaxDynamicSharedMemorySize, AT_SMEM);
    cudaFuncSetAttribute(gemm_mma<0>, cudaFuncAttributeMaxDynamicSharedMemorySize, GSM_TOTAL);
    cudaFuncSetAttribute(gemm_mma<1>, cudaFuncAttributeMaxDynamicSharedMemorySize, GSM_TOTAL);

    const int nA4 = MTOT * DD / 4;
    const int nW4 = DD * DD / 4;
    const dim3 cgA((nA4 + 255) / 256), cgW((nW4 + 255) / 256);
    const dim3 gg(1024 / 128, MTOT / 128);   // (8, 64)

    build_idx<<<BB, 256>>>(mask);

    conv_split<<<cgA, 256>>>(q,  ah, al, nA4);
    conv_split<<<cgW, 256>>>(Wq, wh, wl, nW4);
    gemm_mma<1><<<gg, 256, GSM_TOTAL>>>(ah, al, wh, wl, nullptr, qh, ql, QPRE);

    conv_split<<<cgA, 256>>>(k,  ah, al, nA4);
    conv_split<<<cgW, 256>>>(Wk, wh, wl, nW4);
    gemm_mma<1><<<gg, 256, GSM_TOTAL>>>(ah, al, wh, wl, nullptr, kh, kl, 1.0f);

    conv_split<<<cgA, 256>>>(v,  ah, al, nA4);
    conv_split<<<cgW, 256>>>(Wv, wh, wl, nW4);
    gemm_mma<1><<<gg, 256, GSM_TOTAL>>>(ah, al, wh, wl, nullptr, vh, vl, 1.0f);

    // attention (compacted keys) writes output directly as split planes
    attn_mma<<<dim3(LL / 128, BB * HH), 256, AT_SMEM>>>(ah, al);

    conv_split<<<cgW, 256>>>(Wo, wh, wl, nW4);
    gemm_mma<0><<<gg, 256, GSM_TOTAL>>>(ah, al, wh, wl, out, nullptr, nullptr, 1.0f);
}

// round 15
// speedup vs baseline: 1.1065x; 1.1065x over previous
#include <cuda_runtime.h>
#include <cuda_bf16.h>
#include <cstdint>
#include <math.h>

#define BB  4
#define LL  2048
#define DD  1024
#define HH  16
#define DHH 64
#define MTOT   (BB*LL)            // 8192
#define NPLANE (BB*HH*LL*DHH)     // 8388608
// Q premul: attention scale folded with log2(e) -> softmax in exp2 domain
#define QPRE (0.125f * 1.4426950408889634f)

// ---------------- scratch (__device__ globals are the sanctioned mechanism) --
static __device__ __nv_bfloat16 g_Qh[NPLANE], g_Ql[NPLANE];
static __device__ __nv_bfloat16 g_Kh[NPLANE], g_Kl[NPLANE];
static __device__ __nv_bfloat16 g_Vh[NPLANE], g_Vl[NPLANE];
static __device__ __nv_bfloat16 g_ah[MTOT*DD];   // activation hi plane
static __device__ __nv_bfloat16 g_al[MTOT*DD];   // activation lo plane
static __device__ __nv_bfloat16 g_wh[DD*DD];     // weight hi plane
static __device__ __nv_bfloat16 g_wl[DD*DD];     // weight lo plane
static __device__ int g_idx[BB*LL];              // unmasked key indices (compacted)
static __device__ int g_cnt[BB];                 // unmasked key count per batch

// ---------------- helpers (sm_80-era PTX, valid at .target sm_103) ----------
__device__ __forceinline__ uint32_t smem_u32(const void* p) {
    uint32_t a;
    asm("{ .reg .u64 t; cvta.to.shared.u64 t, %1; cvt.u32.u64 %0, t; }" : "=r"(a) : "l"(p));
    return a;
}
__device__ __forceinline__ void ldsm_x4(uint32_t* r, uint32_t addr) {
    asm volatile("ldmatrix.sync.aligned.m8n8.x4.shared.b16 {%0,%1,%2,%3}, [%4];"
        : "=r"(r[0]), "=r"(r[1]), "=r"(r[2]), "=r"(r[3]) : "r"(addr));
}
__device__ __forceinline__ void ldsm_x4_t(uint32_t* r, uint32_t addr) {
    asm volatile("ldmatrix.sync.aligned.m8n8.x4.trans.shared.b16 {%0,%1,%2,%3}, [%4];"
        : "=r"(r[0]), "=r"(r[1]), "=r"(r[2]), "=r"(r[3]) : "r"(addr));
}
__device__ __forceinline__ void mma16816(float* d, const uint32_t* a, const uint32_t* b) {
    asm volatile("mma.sync.aligned.m16n8k16.row.col.f32.bf16.bf16.f32 "
        "{%0,%1,%2,%3}, {%4,%5,%6,%7}, {%8,%9}, {%0,%1,%2,%3};"
        : "+f"(d[0]), "+f"(d[1]), "+f"(d[2]), "+f"(d[3])
        : "r"(a[0]), "r"(a[1]), "r"(a[2]), "r"(a[3]), "r"(b[0]), "r"(b[1]));
}
__device__ __forceinline__ float ex2f(float x) {
    float y; asm("ex2.approx.ftz.f32 %0, %1;" : "=f"(y) : "f"(x)); return y;
}
__device__ __forceinline__ void split_pair(float a0, float a1, uint32_t& hi, uint32_t& lo) {
    __nv_bfloat162 H = __floats2bfloat162_rn(a0, a1);
    __nv_bfloat162 L = __floats2bfloat162_rn(a0 - __bfloat162float(H.x),
                                             a1 - __bfloat162float(H.y));
    hi = *reinterpret_cast<uint32_t*>(&H);
    lo = *reinterpret_cast<uint32_t*>(&L);
}
__device__ __forceinline__ void cp_async16(uint32_t smem_addr, const void* gptr) {
    asm volatile("cp.async.cg.shared.global [%0], [%1], 16;"
        :: "r"(smem_addr), "l"(gptr) : "memory");
}
#define CP_COMMIT() asm volatile("cp.async.commit_group;" ::: "memory")

// ---------------------------------------------------------------------------
// Per-batch compaction of unmasked key indices (prefix scan over 2048 ints).
// ---------------------------------------------------------------------------
__global__ __launch_bounds__(256)
void build_idx(const int* __restrict__ mask)
{
    __shared__ int ps[256];
    const int b = blockIdx.x, t = threadIdx.x;
    const int* m = mask + b * LL;
    int loc[8], c = 0;
#pragma unroll
    for (int i = 0; i < 8; i++) { loc[i] = m[t * 8 + i]; c += (loc[i] == 1); }
    ps[t] = c;
    __syncthreads();
    for (int off = 1; off < 256; off <<= 1) {
        int u = (t >= off) ? ps[t - off] : 0;
        __syncthreads();
        ps[t] += u;
        __syncthreads();
    }
    int pos = ps[t] - c;        // exclusive prefix
    const int total = ps[255];
#pragma unroll
    for (int i = 0; i < 8; i++)
        if (loc[i] == 1) g_idx[b * LL + (pos++)] = t * 8 + i;
    if (t == 0) {
        g_cnt[b] = total;
        int pad = (total + 63) & ~63;
        for (int i = total; i < pad; i++) g_idx[b * LL + i] = 0;
    }
}

// ---------------------------------------------------------------------------
// fp32 -> (hi, lo) bf16 split conversion
// ---------------------------------------------------------------------------
__global__ __launch_bounds__(256)
void conv_split(const float* __restrict__ in,
                __nv_bfloat16* __restrict__ hi,
                __nv_bfloat16* __restrict__ lo, int n4)
{
    int i = blockIdx.x * blockDim.x + threadIdx.x;
    if (i >= n4) return;
    float4 v = ((const float4*)in)[i];
    uint32_t h01, l01, h23, l23;
    split_pair(v.x, v.y, h01, l01);
    split_pair(v.z, v.w, h23, l23);
    uint32_t* H = (uint32_t*)(hi + 4 * (size_t)i);
    uint32_t* L = (uint32_t*)(lo + 4 * (size_t)i);
    H[0] = h01; H[1] = h23;
    L[0] = l01; L[1] = l23;
}

// ---------------------------------------------------------------------------
// HMMA bf16-split GEMM: C[m,n] = sum_k A[m,k]*W[n,k]
// Register-staged double buffer (R11 scheme) + term-major MMA issue
// (16 independent accumulators between accumulator reuses).
// MODE 0: fp32 C row-major. MODE 1: (hi,lo) bf16 planes, head-split, *premul.
// ---------------------------------------------------------------------------
#define ROWB      80
#define PLANE_B   (128*ROWB)
#define STAGE_B   (4*PLANE_B)
#define GSM_TOTAL (2*STAGE_B)

template<int MODE>
__global__ __launch_bounds__(256)
void gemm_mma(const __nv_bfloat16* __restrict__ Ahp, const __nv_bfloat16* __restrict__ Alp,
              const __nv_bfloat16* __restrict__ Whp, const __nv_bfloat16* __restrict__ Wlp,
              float* __restrict__ Cf,
              __nv_bfloat16* __restrict__ Ch, __nv_bfloat16* __restrict__ Cl,
              float premul)
{
    extern __shared__ char smem[];
    const uint32_t sb = smem_u32(smem);
    const int t    = threadIdx.x;
    const int lane = t & 31;
    const int wid  = t >> 5;
    const int wm   = (wid & 3) * 32;
    const int wn   = (wid >> 2) * 64;
    const int bm   = blockIdx.y * 128;
    const int bn   = blockIdx.x * 128;

    const int r0 = t >> 2,         c80 = (t & 3) * 8;
    const int r1 = (t + 256) >> 2, c81 = ((t + 256) & 3) * 8;

    const __nv_bfloat16* srcA[2] = { Ahp + (size_t)bm * 1024, Alp + (size_t)bm * 1024 };
    const __nv_bfloat16* srcW[2] = { Whp + (size_t)bn * 1024, Wlp + (size_t)bn * 1024 };

    float acc[2][8][4];
#pragma unroll
    for (int i = 0; i < 2; i++)
#pragma unroll
        for (int j = 0; j < 8; j++)
#pragma unroll
            for (int c = 0; c < 4; c++) acc[i][j][c] = 0.f;

    const uint32_t a_row = lane & 15, a_half = (lane >> 4) * 8;
    const uint32_t w_mat = lane >> 3, w_j = lane & 7;
    const uint32_t w_rowoff = (w_mat >> 1) * 8 + w_j;
    const uint32_t w_koff   = (w_mat & 1) * 8;

    uint4 pf[8];
    auto g_load = [&](int chunk) {
        const int k0 = chunk * 32;
#pragma unroll
        for (int p = 0; p < 2; p++) {
            pf[p * 2 + 0] = *(const uint4*)(srcA[p] + (size_t)r0 * 1024 + k0 + c80);
            pf[p * 2 + 1] = *(const uint4*)(srcA[p] + (size_t)r1 * 1024 + k0 + c81);
            pf[4 + p * 2 + 0] = *(const uint4*)(srcW[p] + (size_t)r0 * 1024 + k0 + c80);
            pf[4 + p * 2 + 1] = *(const uint4*)(srcW[p] + (size_t)r1 * 1024 + k0 + c81);
        }
    };
    auto s_store = [&](int st) {
        char* base = smem + st * STAGE_B;
#pragma unroll
        for (int p = 0; p < 4; p++) {
            *(uint4*)(base + p * PLANE_B + r0 * ROWB + c80 * 2) = pf[p * 2 + 0];
            *(uint4*)(base + p * PLANE_B + r1 * ROWB + c81 * 2) = pf[p * 2 + 1];
        }
    };

    g_load(0);
    s_store(0);
    __syncthreads();

    for (int it = 0; it < 32; it++) {
        const int st = it & 1;
        if (it < 31) g_load(it + 1);

        const uint32_t stage = sb + st * STAGE_B;
        const uint32_t ah_b = stage + 0 * PLANE_B;
        const uint32_t al_b = stage + 1 * PLANE_B;
        const uint32_t wh_b = stage + 2 * PLANE_B;
        const uint32_t wl_b = stage + 3 * PLANE_B;

#pragma unroll
        for (int ks = 0; ks < 32; ks += 16) {
            uint32_t ah[2][4], al[2][4], wh[4][4], wl[4][4];
#pragma unroll
            for (int mt = 0; mt < 2; mt++) {
                uint32_t ra = (wm + mt * 16 + a_row) * ROWB + (ks + a_half) * 2;
                ldsm_x4(ah[mt], ah_b + ra);
                ldsm_x4(al[mt], al_b + ra);
            }
#pragma unroll
            for (int np = 0; np < 4; np++) {
                uint32_t rw = (wn + np * 16 + w_rowoff) * ROWB + (ks + w_koff) * 2;
                ldsm_x4(wh[np], wh_b + rw);
                ldsm_x4(wl[np], wl_b + rw);
            }
            // term-major issue: 16 independent accumulators between reuse
#pragma unroll
            for (int mt = 0; mt < 2; mt++)
#pragma unroll
                for (int nt = 0; nt < 8; nt++)
                    mma16816(acc[mt][nt], ah[mt], &wh[nt >> 1][(nt & 1) * 2]);
#pragma unroll
            for (int mt = 0; mt < 2; mt++)
#pragma unroll
                for (int nt = 0; nt < 8; nt++)
                    mma16816(acc[mt][nt], ah[mt], &wl[nt >> 1][(nt & 1) * 2]);
#pragma unroll
            for (int mt = 0; mt < 2; mt++)
#pragma unroll
                for (int nt = 0; nt < 8; nt++)
                    mma16816(acc[mt][nt], al[mt], &wh[nt >> 1][(nt & 1) * 2]);
        }

        if (it < 31) s_store(st ^ 1);
        __syncthreads();
    }

    const int erow = lane >> 2;
    const int ecol = (lane & 3) * 2;
#pragma unroll
    for (int mt = 0; mt < 2; mt++)
#pragma unroll
        for (int nt = 0; nt < 8; nt++)
#pragma unroll
            for (int half = 0; half < 2; half++) {
                int m = bm + wm + mt * 16 + erow + half * 8;
                int n = bn + wn + nt * 8 + ecol;
                float a0 = acc[mt][nt][half * 2 + 0];
                float a1 = acc[mt][nt][half * 2 + 1];
                if (MODE == 1) {
                    a0 *= premul; a1 *= premul;
                    uint32_t hi, lo;
                    split_pair(a0, a1, hi, lo);
                    int bidx = m >> 11, l = m & 2047;
                    int h = n >> 6, dh = n & 63;
                    size_t idx = (((size_t)(bidx * HH + h) * LL + l) << 6) + dh;
                    *(uint32_t*)(Ch + idx) = hi;
                    *(uint32_t*)(Cl + idx) = lo;
                } else {
                    *(float2*)(Cf + (size_t)m * 1024 + n) = make_float2(a0, a1);
                }
            }
}

// ---------------------------------------------------------------------------
// HMMA flash attention over COMPACTED (unmasked) keys, cp.async double-buffer.
// Term-major MMA issue in QK^T and PV. CTA = 128 q rows of one (b,h).
// ---------------------------------------------------------------------------
#define AT_RS    144                  // smem row stride bytes (72 bf16)
#define AT_QH    0
#define AT_QL    18432
#define AT_KVB   36864                // KV stage base
#define KV_STAGE 36864
#define KV_KH    0
#define KV_KL    9216
#define KV_VH    18432
#define KV_VL    27648
#define AT_BIAS  (AT_KVB + 2*KV_STAGE)   // 110592; bias[2][64] floats
#define AT_SMEM  (AT_BIAS + 512)

__global__ __launch_bounds__(256)
void attn_mma(__nv_bfloat16* __restrict__ Oh, __nv_bfloat16* __restrict__ Ol)
{
    extern __shared__ char smc[];
    const uint32_t sb = smem_u32(smc);
    const int t = threadIdx.x, lane = t & 31, wid = t >> 5;
    const int wm = wid * 16;
    const int bh = blockIdx.y;
    const int b  = bh >> 4, h = bh & 15;
    const int r0 = blockIdx.x * 128;
    const size_t pbase = (size_t)bh * LL * DHH;

    const __nv_bfloat16* KH = g_Kh + pbase;
    const __nv_bfloat16* KL = g_Kl + pbase;
    const __nv_bfloat16* VH = g_Vh + pbase;
    const __nv_bfloat16* VL = g_Vl + pbase;

    const int nk     = g_cnt[b];
    const int ntiles = (nk + 63) >> 6;
    const int* idxp  = g_idx + b * LL;

    auto kv_load = [&](int stage, int tile) {
        const uint32_t kvb = sb + AT_KVB + stage * KV_STAGE;
#pragma unroll
        for (int i = 0; i < 2; i++) {
            int slot = i * 256 + t;
            int row = slot >> 3, c8 = (slot & 7) * 8;
            int src = idxp[tile * 64 + row];          // compacted key index
            size_t g = (size_t)src * 64 + c8;
            uint32_t d = kvb + row * AT_RS + c8 * 2;
            cp_async16(d + KV_KH, KH + g);
            cp_async16(d + KV_KL, KL + g);
            cp_async16(d + KV_VH, VH + g);
            cp_async16(d + KV_VL, VL + g);
        }
    };

    // ---- async Q prologue ----
    {
        const __nv_bfloat16* qh = g_Qh + pbase + (size_t)r0 * 64;
        const __nv_bfloat16* ql = g_Ql + pbase + (size_t)r0 * 64;
#pragma unroll
        for (int i = 0; i < 4; i++) {
            int slot = i * 256 + t;
            int row = slot >> 3, c8 = (slot & 7) * 8;
            cp_async16(sb + AT_QH + row * AT_RS + c8 * 2, qh + (size_t)row * 64 + c8);
            cp_async16(sb + AT_QL + row * AT_RS + c8 * 2, ql + (size_t)row * 64 + c8);
        }
        CP_COMMIT();
    }
    kv_load(0, 0);
    CP_COMMIT();
    asm volatile("cp.async.wait_group 1;" ::: "memory");   // Q resident
    __syncthreads();

    // ---- persistent Q fragments ----
    uint32_t qfh[4][4], qfl[4][4];
    {
        uint32_t qa = sb + (wm + (lane & 15)) * AT_RS + (lane >> 4) * 16;
#pragma unroll
        for (int ks = 0; ks < 4; ks++) {
            ldsm_x4(qfh[ks], qa + AT_QH + ks * 32);
            ldsm_x4(qfl[ks], qa + AT_QL + ks * 32);
        }
    }

    const int qr = lane >> 2;
    const int qc = (lane & 3) * 2;
    const int w_mat = lane >> 3;
    const uint32_t kfo = ((w_mat >> 1) * 8 + (lane & 7)) * AT_RS + (w_mat & 1) * 16;
    const uint32_t vfo = ((w_mat & 1) * 8 + (lane & 7)) * AT_RS + (w_mat >> 1) * 16;

    float o[8][4];
#pragma unroll
    for (int i = 0; i < 8; i++)
#pragma unroll
        for (int c = 0; c < 4; c++) o[i][c] = 0.f;
    float mr0 = -1e30f, mr1 = -1e30f, lr0 = 0.f, lr1 = 0.f;

    float* biasp = (float*)(smc + AT_BIAS);

    for (int j = 0; j < ntiles; j++) {
        const int s = j & 1;
        __syncthreads();
        if (j + 1 < ntiles) {
            kv_load(s ^ 1, j + 1);
            CP_COMMIT();
        }
        if (t < 64) biasp[s * 64 + t] = (j * 64 + t < nk) ? 0.f : -1e9f;
        if (j + 1 < ntiles) asm volatile("cp.async.wait_group 1;" ::: "memory");
        else                asm volatile("cp.async.wait_group 0;" ::: "memory");
        __syncthreads();

        const uint32_t kvb = sb + AT_KVB + s * KV_STAGE;

        // ---- S = Q K^T (term-major: 8 indep accs per term) ----
        float sc[8][4];
#pragma unroll
        for (int i = 0; i < 8; i++)
#pragma unroll
            for (int c = 0; c < 4; c++) sc[i][c] = 0.f;

#pragma unroll
        for (int ks = 0; ks < 4; ks++) {
            uint32_t kh4[4][4], kl4[4][4];
#pragma unroll
            for (int g = 0; g < 4; g++) {
                uint32_t a = kvb + kfo + g * (16 * AT_RS) + ks * 32;
                ldsm_x4(kh4[g], a + KV_KH);
                ldsm_x4(kl4[g], a + KV_KL);
            }
#pragma unroll
            for (int nt = 0; nt < 8; nt++)
                mma16816(sc[nt], qfh[ks], &kh4[nt >> 1][(nt & 1) * 2]);
#pragma unroll
            for (int nt = 0; nt < 8; nt++)
                mma16816(sc[nt], qfh[ks], &kl4[nt >> 1][(nt & 1) * 2]);
#pragma unroll
            for (int nt = 0; nt < 8; nt++)
                mma16816(sc[nt], qfl[ks], &kh4[nt >> 1][(nt & 1) * 2]);
        }

        // ---- pad bias + online softmax (exp2 domain) ----
        float m0 = -1e30f, m1 = -1e30f;
#pragma unroll
        for (int nt = 0; nt < 8; nt++) {
            float b0 = biasp[s * 64 + nt * 8 + qc], b1 = biasp[s * 64 + nt * 8 + qc + 1];
            sc[nt][0] += b0; sc[nt][1] += b1; sc[nt][2] += b0; sc[nt][3] += b1;
            m0 = fmaxf(m0, fmaxf(sc[nt][0], sc[nt][1]));
            m1 = fmaxf(m1, fmaxf(sc[nt][2], sc[nt][3]));
        }
        m0 = fmaxf(m0, __shfl_xor_sync(0xffffffffu, m0, 1));
        m0 = fmaxf(m0, __shfl_xor_sync(0xffffffffu, m0, 2));
        m1 = fmaxf(m1, __shfl_xor_sync(0xffffffffu, m1, 1));
        m1 = fmaxf(m1, __shfl_xor_sync(0xffffffffu, m1, 2));

        float mn0 = fmaxf(mr0, m0), mn1 = fmaxf(mr1, m1);
        float al0 = ex2f(mr0 - mn0), al1 = ex2f(mr1 - mn1);
        mr0 = mn0; mr1 = mn1;
        lr0 *= al0; lr1 *= al1;
#pragma unroll
        for (int nt = 0; nt < 8; nt++) {
            sc[nt][0] = ex2f(sc[nt][0] - mn0);
            sc[nt][1] = ex2f(sc[nt][1] - mn0);
            sc[nt][2] = ex2f(sc[nt][2] - mn1);
            sc[nt][3] = ex2f(sc[nt][3] - mn1);
            lr0 += sc[nt][0] + sc[nt][1];
            lr1 += sc[nt][2] + sc[nt][3];
            o[nt][0] *= al0; o[nt][1] *= al0;
            o[nt][2] *= al1; o[nt][3] *= al1;
        }

        // ---- O += P V (hoisted V frags; term-major: 8 indep accs) ----
#pragma unroll
        for (int kk = 0; kk < 4; kk++) {
            const int j0 = kk * 2, j1 = kk * 2 + 1;
            uint32_t ph[4], pl[4];
            split_pair(sc[j0][0], sc[j0][1], ph[0], pl[0]);
            split_pair(sc[j0][2], sc[j0][3], ph[1], pl[1]);
            split_pair(sc[j1][0], sc[j1][1], ph[2], pl[2]);
            split_pair(sc[j1][2], sc[j1][3], ph[3], pl[3]);
            uint32_t vh4[4][4], vl4[4][4];
#pragma unroll
            for (int g = 0; g < 4; g++) {
                uint32_t a = kvb + vfo + kk * (16 * AT_RS) + g * 32;
                ldsm_x4_t(vh4[g], a + KV_VH);
                ldsm_x4_t(vl4[g], a + KV_VL);
            }
#pragma unroll
            for (int nt = 0; nt < 8; nt++)
                mma16816(o[nt], ph, &vh4[nt >> 1][(nt & 1) * 2]);
#pragma unroll
            for (int nt = 0; nt < 8; nt++)
                mma16816(o[nt], ph, &vl4[nt >> 1][(nt & 1) * 2]);
#pragma unroll
            for (int nt = 0; nt < 8; nt++)
                mma16816(o[nt], pl, &vh4[nt >> 1][(nt & 1) * 2]);
        }
    }

    // ---- finalize ----
    lr0 += __shfl_xor_sync(0xffffffffu, lr0, 1);
    lr0 += __shfl_xor_sync(0xffffffffu, lr0, 2);
    lr1 += __shfl_xor_sync(0xffffffffu, lr1, 1);
    lr1 += __shfl_xor_sync(0xffffffffu, lr1, 2);
    const float inv0 = 1.f / lr0, inv1 = 1.f / lr1;

    const size_t m0i = (size_t)b * LL + (r0 + wm + qr);
    const size_t m1i = m0i + 8;
#pragma unroll
    for (int nt = 0; nt < 8; nt++) {
        const int col = h * 64 + nt * 8 + qc;
        uint32_t hi, lo;
        split_pair(o[nt][0] * inv0, o[nt][1] * inv0, hi, lo);
        *(uint32_t*)(Oh + m0i * DD + col) = hi;
        *(uint32_t*)(Ol + m0i * DD + col) = lo;
        split_pair(o[nt][2] * inv1, o[nt][3] * inv1, hi, lo);
        *(uint32_t*)(Oh + m1i * DD + col) = hi;
        *(uint32_t*)(Ol + m1i * DD + col) = lo;
    }
}

// ---------------------------------------------------------------------------
// Launch: 0:q 1:k 2:v 3:mask 4:Wq 5:Wk 6:Wv 7:Wo ; out [B,L,D] fp32
// ---------------------------------------------------------------------------
extern "C" void kernel_launch(void* const* d_in, const int* in_sizes, int n_in,
                              void* d_out, int out_size)
{
    const float* q    = (const float*)d_in[0];
    const float* k    = (const float*)d_in[1];
    const float* v    = (const float*)d_in[2];
    const int*   mask = (const int*)  d_in[3];
    const float* Wq   = (const float*)d_in[4];
    const float* Wk   = (const float*)d_in[5];
    const float* Wv   = (const float*)d_in[6];
    const float* Wo   = (const float*)d_in[7];
    float* out = (float*)d_out;

    __nv_bfloat16 *ah, *al, *wh, *wl, *qh, *ql, *kh, *kl, *vh, *vl;
    cudaGetSymbolAddress((void**)&ah, g_ah);
    cudaGetSymbolAddress((void**)&al, g_al);
    cudaGetSymbolAddress((void**)&wh, g_wh);
    cudaGetSymbolAddress((void**)&wl, g_wl);
    cudaGetSymbolAddress((void**)&qh, g_Qh);
    cudaGetSymbolAddress((void**)&ql, g_Ql);
    cudaGetSymbolAddress((void**)&kh, g_Kh);
    cudaGetSymbolAddress((void**)&kl, g_Kl);
    cudaGetSymbolAddress((void**)&vh, g_Vh);
    cudaGetSymbolAddress((void**)&vl, g_Vl);

    cudaFuncSetAttribute(attn_mma, cudaFuncAttributeMaxDynamicSharedMemorySize, AT_SMEM);
    cudaFuncSetAttribute(gemm_mma<0>, cudaFuncAttributeMaxDynamicSharedMemorySize, GSM_TOTAL);
    cudaFuncSetAttribute(gemm_mma<1>, cudaFuncAttributeMaxDynamicSharedMemorySize, GSM_TOTAL);

    const int nA4 = MTOT * DD / 4;
    const int nW4 = DD * DD / 4;
    const dim3 cgA((nA4 + 255) / 256), cgW((nW4 + 255) / 256);
    const dim3 gg(1024 / 128, MTOT / 128);   // (8, 64)

    build_idx<<<BB, 256>>>(mask);

    conv_split<<<cgA, 256>>>(q,  ah, al, nA4);
    conv_split<<<cgW, 256>>>(Wq, wh, wl, nW4);
    gemm_mma<1><<<gg, 256, GSM_TOTAL>>>(ah, al, wh, wl, nullptr, qh, ql, QPRE);

    conv_split<<<cgA, 256>>>(k,  ah, al, nA4);
    conv_split<<<cgW, 256>>>(Wk, wh, wl, nW4);
    gemm_mma<1><<<gg, 256, GSM_TOTAL>>>(ah, al, wh, wl, nullptr, kh, kl, 1.0f);

    conv_split<<<cgA, 256>>>(v,  ah, al, nA4);
    conv_split<<<cgW, 256>>>(Wv, wh, wl, nW4);
    gemm_mma<1><<<gg, 256, GSM_TOTAL>>>(ah, al, wh, wl, nullptr, vh, vl, 1.0f);

    // attention (compacted keys) writes output directly as split planes
    attn_mma<<<dim3(LL / 128, BB * HH), 256, AT_SMEM>>>(ah, al);

    conv_split<<<cgW, 256>>>(Wo, wh, wl, nW4);
    gemm_mma<0><<<gg, 256, GSM_TOTAL>>>(ah, al, wh, wl, out, nullptr, nullptr, 1.0f);
}